// round 11
// baseline (speedup 1.0000x reference)
#include <cuda_runtime.h>
#include <cuda_bf16.h>
#include <math_constants.h>

// ExactScoreNetwork: out[b,d] = sqrt(1-e_b) * sum_k p_bk * (x_bd - a_b*c_kd) / v_bkd
//   e = exp(-Beta(t)), a = sqrt(e), v = 1 + e*(s^2 - 1)
//   p_bk = softmax_k( -0.5*sum_d diff^2/v - 128*sum_d ln v + ln w_k )
// One warp per batch row (grid=B warps for occupancy), K unrolled by 2 for ILP.
// Per-k invariants (u = s^2-1, log2 w) hoisted into __device__ globals by a prep kernel.

constexpr int K_COMP = 128;
constexpr int D_DIM  = 256;

__device__ float g_u[K_COMP * D_DIM];   // stds^2 - 1
__device__ float g_lw2[K_COMP];         // log2(weights)

__device__ __forceinline__ float frcp(float x){ float r; asm("rcp.approx.ftz.f32 %0, %1;" : "=f"(r) : "f"(x)); return r; }
__device__ __forceinline__ float flg2(float x){ float r; asm("lg2.approx.ftz.f32 %0, %1;" : "=f"(r) : "f"(x)); return r; }
__device__ __forceinline__ float fex2(float x){ float r; asm("ex2.approx.ftz.f32 %0, %1;" : "=f"(r) : "f"(x)); return r; }

// accurate-ish log2: split exponent, lg2.approx on mantissa in [1,2)
__device__ __forceinline__ float log2_acc(float p){
    int b = __float_as_int(p);
    float m = __int_as_float((b & 0x007FFFFF) | 0x3F800000);
    return (float)((b >> 23) - 127) + flg2(m);
}

__global__ void prep_kernel(const float* __restrict__ stds, const float* __restrict__ weights)
{
    int i = blockIdx.x * blockDim.x + threadIdx.x;      // 0 .. K*D-1
    float s = stds[i];
    g_u[i] = fmaf(s, s, -1.0f);
    if (i < K_COMP) g_lw2[i] = log2f(weights[i]);
}

__global__ void __launch_bounds__(32)
score_kernel(const float* __restrict__ x, const float* __restrict__ t,
             const float* __restrict__ centers, float* __restrict__ out)
{
    const int lane = threadIdx.x;
    const int b    = blockIdx.x;

    float tt = t[b];
    float Bt = fmaf(9.95f, tt * tt, 0.1f * tt);   // Beta(t) = 0.1 t + 9.95 t^2
    float e  = expf(-Bt);                          // accurate: matters for 1-e at small t
    const float ev  = e;
    const float na  = -sqrtf(e);                   // -a
    const float osc = sqrtf(fmaxf(1.0f - e, 0.0f));

    float xr[8], acc[8];
    {
        const float4* xp = reinterpret_cast<const float4*>(x + (size_t)b * D_DIM + lane * 8);
        float4 x0 = xp[0], x1 = xp[1];
        xr[0]=x0.x; xr[1]=x0.y; xr[2]=x0.z; xr[3]=x0.w;
        xr[4]=x1.x; xr[5]=x1.y; xr[6]=x1.z; xr[7]=x1.w;
    }
    #pragma unroll
    for (int j = 0; j < 8; j++) acc[j] = 0.0f;
    float mx  = -CUDART_INF_F;                     // log2-domain running max
    float den = 0.0f;

    #pragma unroll 1
    for (int k = 0; k < K_COMP; k += 2) {
        const float4* cp0 = reinterpret_cast<const float4*>(centers + (size_t)k * D_DIM + lane * 8);
        const float4* up0 = reinterpret_cast<const float4*>(g_u     + (size_t)k * D_DIM + lane * 8);
        const float4* cp1 = cp0 + (D_DIM / 4);
        const float4* up1 = up0 + (D_DIM / 4);

        float4 ca0 = __ldg(cp0), ca1 = __ldg(cp0 + 1);
        float4 ua0 = __ldg(up0), ua1 = __ldg(up0 + 1);
        float4 cb0 = __ldg(cp1), cb1 = __ldg(cp1 + 1);
        float4 ub0 = __ldg(up1), ub1 = __ldg(up1 + 1);

        float c0[8] = {ca0.x,ca0.y,ca0.z,ca0.w,ca1.x,ca1.y,ca1.z,ca1.w};
        float u0[8] = {ua0.x,ua0.y,ua0.z,ua0.w,ua1.x,ua1.y,ua1.z,ua1.w};
        float c1[8] = {cb0.x,cb0.y,cb0.z,cb0.w,cb1.x,cb1.y,cb1.z,cb1.w};
        float u1[8] = {ub0.x,ub0.y,ub0.z,ub0.w,ub1.x,ub1.y,ub1.z,ub1.w};

        float g0[8], g1[8];
        float q0 = 0.0f, p0v = 1.0f, q1 = 0.0f, p1v = 1.0f;
        #pragma unroll
        for (int j = 0; j < 8; j++) {
            float v0  = fmaf(ev, u0[j], 1.0f);     // in [0.25, 1]
            float v1  = fmaf(ev, u1[j], 1.0f);
            float rv0 = frcp(v0);
            float rv1 = frcp(v1);
            float d0  = fmaf(na, c0[j], xr[j]);
            float d1  = fmaf(na, c1[j], xr[j]);
            float gg0 = d0 * rv0;
            float gg1 = d1 * rv1;
            q0 = fmaf(d0, gg0, q0);                // sum diff^2 / v
            q1 = fmaf(d1, gg1, q1);
            p0v *= v0;                             // chunk product for log-det
            p1v *= v1;
            g0[j] = gg0;                           // diff / v (grad piece)
            g1[j] = gg1;
        }
        // per-lane combined log2-domain partial: z = -0.5*log2e*q - 128*log2(prod)
        float z0 = fmaf(-0.72134752044448170f, q0, -128.0f * log2_acc(p0v));
        float z1 = fmaf(-0.72134752044448170f, q1, -128.0f * log2_acc(p1v));

        // interleaved warp reductions (independent shfl chains)
        #pragma unroll
        for (int off = 16; off >= 1; off >>= 1) {
            z0 += __shfl_xor_sync(0xffffffffu, z0, off);
            z1 += __shfl_xor_sync(0xffffffffu, z1, off);
        }

        // fused branchless online-softmax update for the pair (log2 domain)
        float lp0 = z0 + g_lw2[k];
        float lp1 = z1 + g_lw2[k + 1];
        float mn  = fmaxf(mx, fmaxf(lp0, lp1));
        float sc  = fex2(mx - mn);                 // ex2(-inf)=0 on first pair
        float p0  = fex2(lp0 - mn);
        float p1  = fex2(lp1 - mn);
        den = fmaf(den, sc, p0 + p1);
        #pragma unroll
        for (int j = 0; j < 8; j++)
            acc[j] = fmaf(acc[j], sc, fmaf(p0, g0[j], p1 * g1[j]));
        mx = mn;
    }

    float s = osc * frcp(den);
    float4 o0, o1;
    o0.x = acc[0]*s; o0.y = acc[1]*s; o0.z = acc[2]*s; o0.w = acc[3]*s;
    o1.x = acc[4]*s; o1.y = acc[5]*s; o1.z = acc[6]*s; o1.w = acc[7]*s;
    float4* op = reinterpret_cast<float4*>(out + (size_t)b * D_DIM + lane * 8);
    op[0] = o0; op[1] = o1;
}

extern "C" void kernel_launch(void* const* d_in, const int* in_sizes, int n_in,
                              void* d_out, int out_size)
{
    const float* x       = (const float*)d_in[0];   // [B, 256]
    const float* t       = (const float*)d_in[1];   // [B]
    const float* centers = (const float*)d_in[2];   // [128, 256]
    const float* stds    = (const float*)d_in[3];   // [128, 256]
    const float* weights = (const float*)d_in[4];   // [128]
    float* out = (float*)d_out;                      // [B, 256]

    int B = in_sizes[1];                             // t element count

    prep_kernel<<<(K_COMP * D_DIM) / 128, 128>>>(stds, weights);
    score_kernel<<<B, 32>>>(x, t, centers, out);
}

// round 13
// speedup vs baseline: 1.1496x; 1.1496x over previous
#include <cuda_runtime.h>
#include <cuda_bf16.h>
#include <math_constants.h>

// ExactScoreNetwork: out[b,d] = sqrt(1-e_b) * sum_k p_bk * (x_bd - a_b*c_kd) / v_bkd
//   e = exp(-Beta(t)), a = sqrt(e), v = 1 + e*(s^2 - 1)
//   p_bk = softmax_k( -0.5*sum_d diff^2/v - 128*sum_d ln v + ln w_k )
//
// Layout: CTA = 64 threads (2 warps) handles 2 batch rows.
//   Both warps keep BOTH rows in registers; warp w processes K-half [w*64, w*64+64).
//   Center/u loads are shared across the 2 rows (halves L1 traffic vs 1 row/warp),
//   warp count stays B (4096) for occupancy. K-half softmax states merge via smem.
// Warp reductions: two interleaved 5-step shfl_xor butterflies (redux.f32 is not
// available on sm_103 — ptxas rejects it).

constexpr int K_COMP = 128;
constexpr int D_DIM  = 256;
constexpr int KHALF  = K_COMP / 2;

__device__ float g_u[K_COMP * D_DIM];   // stds^2 - 1
__device__ float g_lw2[K_COMP];         // log2(weights)

__device__ __forceinline__ float frcp(float x){ float r; asm("rcp.approx.ftz.f32 %0, %1;" : "=f"(r) : "f"(x)); return r; }
__device__ __forceinline__ float flg2(float x){ float r; asm("lg2.approx.ftz.f32 %0, %1;" : "=f"(r) : "f"(x)); return r; }
__device__ __forceinline__ float fex2(float x){ float r; asm("ex2.approx.ftz.f32 %0, %1;" : "=f"(r) : "f"(x)); return r; }

// accurate-ish log2: split exponent, lg2.approx on mantissa in [1,2)
__device__ __forceinline__ float log2_acc(float p){
    int b = __float_as_int(p);
    float m = __int_as_float((b & 0x007FFFFF) | 0x3F800000);
    return (float)((b >> 23) - 127) + flg2(m);
}

__global__ void prep_kernel(const float* __restrict__ stds, const float* __restrict__ weights)
{
    int i = blockIdx.x * blockDim.x + threadIdx.x;      // 0 .. K*D-1
    float s = stds[i];
    g_u[i] = fmaf(s, s, -1.0f);
    if (i < K_COMP) g_lw2[i] = log2f(weights[i]);
}

__global__ void __launch_bounds__(64)
score_kernel(const float* __restrict__ x, const float* __restrict__ t,
             const float* __restrict__ centers, float* __restrict__ out)
{
    __shared__ float s_acc[2][32][8];
    __shared__ float s_mx[2], s_den[2];

    const int lane = threadIdx.x & 31;
    const int w    = threadIdx.x >> 5;          // warp id in CTA: K-half selector
    const int b0   = blockIdx.x * 2;            // two rows per CTA

    // per-row scalars (both warps compute both rows)
    float ev[2], na[2], osc[2];
    float xr[2][8], acc[2][8], mx[2], den[2];
    #pragma unroll
    for (int r = 0; r < 2; r++) {
        float tt = t[b0 + r];
        float Bt = fmaf(9.95f, tt * tt, 0.1f * tt);   // Beta(t) = 0.1 t + 9.95 t^2
        float e  = expf(-Bt);                          // accurate: matters for 1-e at small t
        ev[r]  = e;
        na[r]  = -sqrtf(e);                            // -a
        osc[r] = sqrtf(fmaxf(1.0f - e, 0.0f));
        const float4* xp = reinterpret_cast<const float4*>(x + (size_t)(b0 + r) * D_DIM + lane * 8);
        float4 x0 = xp[0], x1 = xp[1];
        xr[r][0]=x0.x; xr[r][1]=x0.y; xr[r][2]=x0.z; xr[r][3]=x0.w;
        xr[r][4]=x1.x; xr[r][5]=x1.y; xr[r][6]=x1.z; xr[r][7]=x1.w;
        #pragma unroll
        for (int j = 0; j < 8; j++) acc[r][j] = 0.0f;
        mx[r]  = -CUDART_INF_F;                        // log2-domain running max
        den[r] = 0.0f;
    }

    const int kbeg = w * KHALF;
    #pragma unroll 1
    for (int k = kbeg; k < kbeg + KHALF; k++) {
        const float4* cp = reinterpret_cast<const float4*>(centers + (size_t)k * D_DIM + lane * 8);
        const float4* up = reinterpret_cast<const float4*>(g_u     + (size_t)k * D_DIM + lane * 8);
        float4 c0 = __ldg(cp), c1 = __ldg(cp + 1);
        float4 u0 = __ldg(up), u1 = __ldg(up + 1);
        float c[8] = {c0.x,c0.y,c0.z,c0.w,c1.x,c1.y,c1.z,c1.w};
        float u[8] = {u0.x,u0.y,u0.z,u0.w,u1.x,u1.y,u1.z,u1.w};
        float lw2 = g_lw2[k];

        // both rows share c/u; interleaved for ILP
        float g[2][8];
        float q0 = 0.0f, q1 = 0.0f, pr0 = 1.0f, pr1 = 1.0f;
        #pragma unroll
        for (int j = 0; j < 8; j++) {
            float v0  = fmaf(ev[0], u[j], 1.0f);       // in [0.25, 1]
            float v1  = fmaf(ev[1], u[j], 1.0f);
            float rv0 = frcp(v0);
            float rv1 = frcp(v1);
            float d0  = fmaf(na[0], c[j], xr[0][j]);
            float d1  = fmaf(na[1], c[j], xr[1][j]);
            float g0  = d0 * rv0;
            float g1  = d1 * rv1;
            q0 = fmaf(d0, g0, q0);                     // sum diff^2 / v
            q1 = fmaf(d1, g1, q1);
            pr0 *= v0;                                 // chunk product for log-det
            pr1 *= v1;
            g[0][j] = g0;                              // diff / v (grad piece)
            g[1][j] = g1;
        }
        // per-lane combined log2-domain partial: z = -0.5*log2e*q - 128*log2(prod)
        float z0 = fmaf(-0.72134752044448170f, q0, -128.0f * log2_acc(pr0));
        float z1 = fmaf(-0.72134752044448170f, q1, -128.0f * log2_acc(pr1));

        // two interleaved independent butterfly reductions (latency overlap)
        #pragma unroll
        for (int off = 16; off >= 1; off >>= 1) {
            z0 += __shfl_xor_sync(0xffffffffu, z0, off);
            z1 += __shfl_xor_sync(0xffffffffu, z1, off);
        }

        // branchless online softmax update per row (log2 domain)
        float lp0 = z0 + lw2;
        float lp1 = z1 + lw2;
        float mn0 = fmaxf(mx[0], lp0);
        float mn1 = fmaxf(mx[1], lp1);
        float sc0 = fex2(mx[0] - mn0);                 // ex2(-inf)=0 on first k
        float sc1 = fex2(mx[1] - mn1);
        float p0  = fex2(lp0 - mn0);
        float p1  = fex2(lp1 - mn1);
        den[0] = fmaf(den[0], sc0, p0);
        den[1] = fmaf(den[1], sc1, p1);
        #pragma unroll
        for (int j = 0; j < 8; j++) {
            acc[0][j] = fmaf(acc[0][j], sc0, p0 * g[0][j]);
            acc[1][j] = fmaf(acc[1][j], sc1, p1 * g[1][j]);
        }
        mx[0] = mn0;
        mx[1] = mn1;
    }

    // ── merge the two K-half states ──
    // warp w merges row (rm = w); it exports its OTHER row (ro = 1-w) to smem slot w.
    const int rm = w, ro = 1 - w;
    #pragma unroll
    for (int j = 0; j < 8; j++) s_acc[w][lane][j] = acc[ro][j];
    if (lane == 0) { s_mx[w] = mx[ro]; s_den[w] = den[ro]; }
    __syncthreads();

    float omx  = s_mx[ro];                 // partner warp's state for row rm
    float oden = s_den[ro];
    float mn = fmaxf(mx[rm], omx);
    float sa = fex2(mx[rm] - mn);
    float sb = fex2(omx - mn);
    float dtot = fmaf(den[rm], sa, oden * sb);
    float s = osc[rm] * frcp(dtot);

    float4 o0, o1;
    float oacc[8];
    #pragma unroll
    for (int j = 0; j < 8; j++)
        oacc[j] = fmaf(acc[rm][j], sa, s_acc[ro][lane][j] * sb) * s;
    o0.x = oacc[0]; o0.y = oacc[1]; o0.z = oacc[2]; o0.w = oacc[3];
    o1.x = oacc[4]; o1.y = oacc[5]; o1.z = oacc[6]; o1.w = oacc[7];
    float4* op = reinterpret_cast<float4*>(out + (size_t)(b0 + rm) * D_DIM + lane * 8);
    op[0] = o0; op[1] = o1;
}

extern "C" void kernel_launch(void* const* d_in, const int* in_sizes, int n_in,
                              void* d_out, int out_size)
{
    const float* x       = (const float*)d_in[0];   // [B, 256]
    const float* t       = (const float*)d_in[1];   // [B]
    const float* centers = (const float*)d_in[2];   // [128, 256]
    const float* stds    = (const float*)d_in[3];   // [128, 256]
    const float* weights = (const float*)d_in[4];   // [128]
    float* out = (float*)d_out;                      // [B, 256]

    int B = in_sizes[1];                             // t element count

    prep_kernel<<<(K_COMP * D_DIM) / 128, 128>>>(stds, weights);
    score_kernel<<<B / 2, 64>>>(x, t, centers, out);
}